// round 1
// baseline (speedup 1.0000x reference)
#include <cuda_runtime.h>
#include <math.h>

#define L      512
#define NS     8192      // samples per row
#define NREF   8192      // reference grid points
#define G      (3*NREF)  // 24576 ecdf grid points
#define NB     8192      // buckets for counting sort
#define TPB    1024

// Scratch: h for all 1024 distribution rows (x1 rows 0..511, x2 rows 512..1023)
__device__ float g_h[2 * L * NREF];   // 32 MB
__device__ float g_rowsum[L];

// ---------------------------------------------------------------------------
// Per-row kernel: sort -> cdf -> ecdf grid -> inverse interp -> h
// One block (1024 threads) per distribution row. Dynamic smem layout:
//   s_key [8192] floats   (sorted samples)
//   s_val [8192] floats   (weights, becomes cdf after scan)
//   s_ecdf[24576] floats  (also reused as int histogram/cursors early on)
//   s_off [8193] ints     (bucket exclusive offsets, kept for fast lower_bound)
// ---------------------------------------------------------------------------
extern "C" __global__ void __launch_bounds__(TPB, 1)
lcot_row_kernel(const float* __restrict__ x1, const float* __restrict__ w1,
                const float* __restrict__ x2, const float* __restrict__ w2)
{
    extern __shared__ float sm[];
    float* s_key  = sm;
    float* s_val  = sm + NS;
    float* s_ecdf = sm + 2 * NS;
    int*   s_off  = (int*)(sm + 2 * NS + G);
    int*   s_hist = (int*)s_ecdf;          // aliased: used before ecdf phase

    __shared__ float s_redA[32];
    __shared__ float s_redB[32];
    __shared__ int   s_wsum[32];
    __shared__ float s_alpha;
    __shared__ int   s_flag;

    const int b   = blockIdx.x;            // 0..1023
    const int tid = threadIdx.x;
    const int lane = tid & 31, wid = tid >> 5;
    const float* __restrict__ xp = (b < L ? x1 : x2) + (b & (L - 1)) * NS;
    const float* __restrict__ wp = (b < L ? w1 : w2) + (b & (L - 1)) * NS;

    // ---- Phase 0: alpha = sum(x*w)/sum(w) - 0.5 ; zero histogram ----
    float sw = 0.f, sxw = 0.f;
    for (int i = tid; i < NS; i += TPB) {
        float x = xp[i], w = wp[i];
        sw += w; sxw += x * w;
    }
    #pragma unroll
    for (int o = 16; o; o >>= 1) {
        sw  += __shfl_down_sync(0xffffffffu, sw,  o);
        sxw += __shfl_down_sync(0xffffffffu, sxw, o);
    }
    if (lane == 0) { s_redA[wid] = sw; s_redB[wid] = sxw; }
    for (int i = tid; i < NB; i += TPB) s_hist[i] = 0;
    __syncthreads();
    if (tid == 0) {
        float a = 0.f, c = 0.f;
        #pragma unroll
        for (int i = 0; i < TPB / 32; i++) { a += s_redA[i]; c += s_redB[i]; }
        s_alpha = c / a - 0.5f;
    }

    // ---- Phase A: histogram ----
    for (int i = tid; i < NS; i += TPB) {
        int bk = (int)(xp[i] * (float)NB);
        bk = bk < 0 ? 0 : (bk > NB - 1 ? NB - 1 : bk);
        atomicAdd(&s_hist[bk], 1);
    }
    __syncthreads();

    // ---- Phase B: exclusive scan of histogram -> s_off ----
    {
        int loc[8]; int tsum = 0; const int base = tid * 8;
        #pragma unroll
        for (int j = 0; j < 8; j++) { loc[j] = tsum; tsum += s_hist[base + j]; }
        int v = tsum;
        #pragma unroll
        for (int o = 1; o < 32; o <<= 1) {
            int t = __shfl_up_sync(0xffffffffu, v, o);
            if (lane >= o) v += t;
        }
        if (lane == 31) s_wsum[wid] = v;
        __syncthreads();
        if (wid == 0) {
            int t = s_wsum[lane];
            #pragma unroll
            for (int o = 1; o < 32; o <<= 1) {
                int u = __shfl_up_sync(0xffffffffu, t, o);
                if (lane >= o) t += u;
            }
            s_wsum[lane] = t;
        }
        __syncthreads();
        const int woff = (wid > 0) ? s_wsum[wid - 1] : 0;
        const int toff = woff + (v - tsum);
        #pragma unroll
        for (int j = 0; j < 8; j++) s_off[base + j] = toff + loc[j];
        if (tid == TPB - 1) s_off[NS] = toff + tsum;   // == NS
    }
    __syncthreads();

    // cursors = copy of offsets (s_hist aliases s_ecdf; ecdf not written yet)
    for (int i = tid; i < NB; i += TPB) s_hist[i] = s_off[i];
    __syncthreads();

    // ---- Phase C: scatter into buckets ----
    for (int i = tid; i < NS; i += TPB) {
        float x = xp[i], w = wp[i];
        int bk = (int)(x * (float)NB);
        bk = bk < 0 ? 0 : (bk > NB - 1 ? NB - 1 : bk);
        int p = atomicAdd(&s_hist[bk], 1);
        s_key[p] = x; s_val[p] = w;
    }
    if (tid == 0) s_flag = 0;
    __syncthreads();

    // ---- Phase D: odd-even cleanup until fully sorted (lexicographic on
    //      (key, weight) -> deterministic output despite atomic scatter) ----
    for (;;) {
        for (int i = tid; i < NS / 2; i += TPB) {              // even pairs
            int p = 2 * i;
            float k0 = s_key[p], k1 = s_key[p + 1];
            float v0 = s_val[p], v1 = s_val[p + 1];
            if (k0 > k1 || (k0 == k1 && v0 > v1)) {
                s_key[p] = k1; s_key[p + 1] = k0;
                s_val[p] = v1; s_val[p + 1] = v0;
                s_flag = 1;
            }
        }
        __syncthreads();
        for (int i = tid; i < NS / 2; i += TPB) {              // odd pairs
            int p = 2 * i + 1;
            if (p + 1 < NS) {
                float k0 = s_key[p], k1 = s_key[p + 1];
                float v0 = s_val[p], v1 = s_val[p + 1];
                if (k0 > k1 || (k0 == k1 && v0 > v1)) {
                    s_key[p] = k1; s_key[p + 1] = k0;
                    s_val[p] = v1; s_val[p + 1] = v0;
                    s_flag = 1;
                }
            }
        }
        __syncthreads();
        int sw2 = s_flag;
        __syncthreads();
        if (!sw2) break;
        if (tid == 0) s_flag = 0;
        __syncthreads();
    }

    // ---- Phase E: inclusive scan of weights -> cdf (in place in s_val) ----
    {
        float loc[8]; float tsum = 0.f; const int base = tid * 8;
        #pragma unroll
        for (int j = 0; j < 8; j++) { tsum += s_val[base + j]; loc[j] = tsum; }
        float v = tsum;
        #pragma unroll
        for (int o = 1; o < 32; o <<= 1) {
            float t = __shfl_up_sync(0xffffffffu, v, o);
            if (lane >= o) v += t;
        }
        if (lane == 31) s_redA[wid] = v;
        __syncthreads();
        if (wid == 0) {
            float t = s_redA[lane];
            #pragma unroll
            for (int o = 1; o < 32; o <<= 1) {
                float u = __shfl_up_sync(0xffffffffu, t, o);
                if (lane >= o) t += u;
            }
            s_redA[lane] = t;
        }
        __syncthreads();
        const float woff = (wid > 0) ? s_redA[wid - 1] : 0.f;
        const float toff = woff + (v - tsum);
        #pragma unroll
        for (int j = 0; j < 8; j++) s_val[base + j] = toff + loc[j];
    }
    __syncthreads();

    // ---- Phase F: ecdf on the 3N grid. lower_bound accelerated by bucket
    //      offsets: answer lies in [off[bk], off[bk+1]] (monotone mapping). ----
    const double step = 3.0 / (double)(G - 1);
    for (int g = tid; g < G; g += TPB) {
        float xn = (float)(-1.0 + step * (double)g);
        float fx = floorf(xn);
        float r  = xn - fx;                       // in [0,1)
        int bk = (int)(r * (float)NB);
        bk = bk < 0 ? 0 : (bk > NB - 1 ? NB - 1 : bk);
        int lb = s_off[bk], hi = s_off[bk + 1];
        while (lb < hi && s_key[lb] < r) lb++;    // expected ~1 iteration
        int idx = lb - 1;
        idx = idx < 0 ? 0 : (idx > NS - 2 ? NS - 2 : idx);
        float x0 = s_key[idx], x1v = s_key[idx + 1];
        float y0 = s_val[idx], y1v = s_val[idx + 1];
        float t  = (r - x0) / (x1v - x0);
        s_ecdf[g] = fx + (y0 + t * (y1v - y0));
    }
    __syncthreads();

    // ---- Phase G: invert ecdf at queries q_i = i/N - alpha (sorted ->
    //      binary search once per 8-query chunk, then merge-advance) ----
    const float alpha = s_alpha;
    float* __restrict__ hout = g_h + (size_t)b * NREF;
    int lb;
    {
        float q0 = (float)(tid * 8) * (1.0f / NREF) - alpha;
        int lo = 0, hi2 = G;
        while (lo < hi2) {
            int mid = (lo + hi2) >> 1;
            if (s_ecdf[mid] < q0) lo = mid + 1; else hi2 = mid;
        }
        lb = lo;
    }
    #pragma unroll
    for (int j = 0; j < 8; j++) {
        int i = tid * 8 + j;
        float refv = (float)i * (1.0f / NREF);
        float q = refv - alpha;
        while (lb < G && s_ecdf[lb] < q) lb++;
        int idx = lb - 1;
        idx = idx < 0 ? 0 : (idx > G - 2 ? G - 2 : idx);
        float e0 = s_ecdf[idx], e1 = s_ecdf[idx + 1];
        float xn0 = (float)(-1.0 + step * (double)idx);
        float xn1 = (float)(-1.0 + step * (double)(idx + 1));
        float t = (q - e0) / (e1 - e0);
        hout[i] = xn0 + t * (xn1 - xn0) - refv;
    }
}

// ---------------------------------------------------------------------------
// Reduce: per-row sum of min(d, 1-d)^2   (no atomics -> deterministic)
// ---------------------------------------------------------------------------
extern "C" __global__ void lcot_reduce_kernel()
{
    const int row = blockIdx.x;                 // 0..511
    const float* __restrict__ h1 = g_h + (size_t)row * NREF;
    const float* __restrict__ h2 = g_h + (size_t)(L + row) * NREF;
    float s = 0.f;
    for (int i = threadIdx.x; i < NREF; i += blockDim.x) {
        float d = fabsf(h2[i] - h1[i]);
        float m = fminf(d, 1.0f - d);
        s += m * m;
    }
    #pragma unroll
    for (int o = 16; o; o >>= 1) s += __shfl_down_sync(0xffffffffu, s, o);
    __shared__ float r[8];
    int lane = threadIdx.x & 31, wid = threadIdx.x >> 5;
    if (lane == 0) r[wid] = s;
    __syncthreads();
    if (threadIdx.x == 0) {
        float tot = 0.f;
        #pragma unroll
        for (int i = 0; i < 8; i++) tot += r[i];
        g_rowsum[row] = tot;
    }
}

// Finalize: deterministic fixed-tree sum of 512 row sums, sqrt(mean)
extern "C" __global__ void lcot_fin_kernel(float* __restrict__ out)
{
    __shared__ double sd[512];
    sd[threadIdx.x] = (double)g_rowsum[threadIdx.x];
    __syncthreads();
    #pragma unroll
    for (int o = 256; o; o >>= 1) {
        if (threadIdx.x < o) sd[threadIdx.x] += sd[threadIdx.x + o];
        __syncthreads();
    }
    if (threadIdx.x == 0) out[0] = (float)sqrt(sd[0] / (double)L);
}

extern "C" void kernel_launch(void* const* d_in, const int* in_sizes, int n_in,
                              void* d_out, int out_size)
{
    const float* x1 = (const float*)d_in[0];
    const float* w1 = (const float*)d_in[1];
    const float* x2 = (const float*)d_in[2];
    const float* w2 = (const float*)d_in[3];
    float* out = (float*)d_out;

    const size_t smem = (size_t)(2 * NS + G) * sizeof(float)
                      + (size_t)(NB + 1) * sizeof(int);   // 196612 bytes
    cudaFuncSetAttribute(lcot_row_kernel,
                         cudaFuncAttributeMaxDynamicSharedMemorySize, (int)smem);

    lcot_row_kernel<<<2 * L, TPB, smem>>>(x1, w1, x2, w2);
    lcot_reduce_kernel<<<L, 256>>>();
    lcot_fin_kernel<<<1, 512>>>(out);
}

// round 2
// speedup vs baseline: 1.0196x; 1.0196x over previous
#include <cuda_runtime.h>
#include <math.h>

#define L      512
#define NS     8192      // samples per row
#define NREF   8192      // reference grid points
#define G      (3*NREF)  // 24576 ecdf grid points
#define NB     8192      // buckets for counting sort
#define TPB    1024

// Scratch: h for all 1024 distribution rows (x1 rows 0..511, x2 rows 512..1023)
__device__ float g_h[2 * L * NREF];   // 32 MB
__device__ float g_rowsum[L];

// ---------------------------------------------------------------------------
// Per-row kernel: bucket sort -> cdf -> ecdf grid -> inverse interp -> h
// One block (1024 threads) per distribution row. Dynamic smem layout:
//   s_key [8192] floats   (sorted samples)
//   s_val [8192] floats   (weights, becomes cdf after scan)
//   s_ecdf[24576] floats  (aliased as int histogram/cursors before ecdf phase)
//   s_off [8193] ints     (bucket exclusive offsets; fast lower_bound table)
// ---------------------------------------------------------------------------
extern "C" __global__ void __launch_bounds__(TPB, 1)
lcot_row_kernel(const float* __restrict__ x1, const float* __restrict__ w1,
                const float* __restrict__ x2, const float* __restrict__ w2)
{
    extern __shared__ float sm[];
    float* s_key  = sm;
    float* s_val  = sm + NS;
    float* s_ecdf = sm + 2 * NS;
    int*   s_off  = (int*)(sm + 2 * NS + G);
    int*   s_hist = (int*)s_ecdf;          // aliased: used before ecdf phase

    __shared__ float s_redA[32];
    __shared__ float s_redB[32];
    __shared__ int   s_wsum[32];
    __shared__ float s_alpha;

    const int b   = blockIdx.x;            // 0..1023
    const int tid = threadIdx.x;
    const int lane = tid & 31, wid = tid >> 5;
    const float* __restrict__ xp = (b < L ? x1 : x2) + (b & (L - 1)) * NS;
    const float* __restrict__ wp = (b < L ? w1 : w2) + (b & (L - 1)) * NS;

    // ---- Phase 0: zero histogram ----
    for (int i = tid; i < NB; i += TPB) s_hist[i] = 0;
    __syncthreads();

    // ---- Phase A (fused): alpha sums + histogram in one global pass ----
    float sw = 0.f, sxw = 0.f;
    for (int i = tid; i < NS; i += TPB) {
        float x = xp[i], w = wp[i];
        sw += w; sxw += x * w;
        int bk = (int)(x * (float)NB);
        bk = bk < 0 ? 0 : (bk > NB - 1 ? NB - 1 : bk);
        atomicAdd(&s_hist[bk], 1);
    }
    #pragma unroll
    for (int o = 16; o; o >>= 1) {
        sw  += __shfl_down_sync(0xffffffffu, sw,  o);
        sxw += __shfl_down_sync(0xffffffffu, sxw, o);
    }
    if (lane == 0) { s_redA[wid] = sw; s_redB[wid] = sxw; }
    __syncthreads();
    if (tid == 0) {
        float a = 0.f, c = 0.f;
        #pragma unroll
        for (int i = 0; i < TPB / 32; i++) { a += s_redA[i]; c += s_redB[i]; }
        s_alpha = c / a - 0.5f;
    }

    // ---- Phase B: exclusive scan of histogram -> s_off ----
    {
        int loc[8]; int tsum = 0; const int base = tid * 8;
        #pragma unroll
        for (int j = 0; j < 8; j++) { loc[j] = tsum; tsum += s_hist[base + j]; }
        int v = tsum;
        #pragma unroll
        for (int o = 1; o < 32; o <<= 1) {
            int t = __shfl_up_sync(0xffffffffu, v, o);
            if (lane >= o) v += t;
        }
        if (lane == 31) s_wsum[wid] = v;
        __syncthreads();
        if (wid == 0) {
            int t = s_wsum[lane];
            #pragma unroll
            for (int o = 1; o < 32; o <<= 1) {
                int u = __shfl_up_sync(0xffffffffu, t, o);
                if (lane >= o) t += u;
            }
            s_wsum[lane] = t;
        }
        __syncthreads();
        const int woff = (wid > 0) ? s_wsum[wid - 1] : 0;
        const int toff = woff + (v - tsum);
        #pragma unroll
        for (int j = 0; j < 8; j++) s_off[base + j] = toff + loc[j];
        if (tid == TPB - 1) s_off[NS] = toff + tsum;   // == NS
    }
    __syncthreads();

    // cursors = copy of offsets (s_hist aliases s_ecdf; ecdf not written yet)
    for (int i = tid; i < NB; i += TPB) s_hist[i] = s_off[i];
    __syncthreads();

    // ---- Phase C: scatter into buckets ----
    for (int i = tid; i < NS; i += TPB) {
        float x = xp[i], w = wp[i];
        int bk = (int)(x * (float)NB);
        bk = bk < 0 ? 0 : (bk > NB - 1 ? NB - 1 : bk);
        int p = atomicAdd(&s_hist[bk], 1);
        s_key[p] = x; s_val[p] = w;
    }
    __syncthreads();

    // ---- Phase D: per-bucket insertion sort. Buckets partition the sorted
    //      order (x -> bucket map is monotone), so this is fully parallel.
    //      Lexicographic (key, weight) comparator -> deterministic result
    //      regardless of atomic scatter order. One barrier, no loop. ----
    for (int bk = tid; bk < NB; bk += TPB) {
        const int lo = s_off[bk], hi = s_off[bk + 1];
        for (int i = lo + 1; i < hi; i++) {
            float k = s_key[i], v = s_val[i];
            int j = i - 1;
            while (j >= lo) {
                float kj = s_key[j];
                if (kj > k || (kj == k && s_val[j] > v)) {
                    s_key[j + 1] = kj; s_val[j + 1] = s_val[j]; j--;
                } else break;
            }
            s_key[j + 1] = k; s_val[j + 1] = v;
        }
    }
    __syncthreads();

    // ---- Phase E: inclusive scan of weights -> cdf (in place in s_val) ----
    {
        float loc[8]; float tsum = 0.f; const int base = tid * 8;
        #pragma unroll
        for (int j = 0; j < 8; j++) { tsum += s_val[base + j]; loc[j] = tsum; }
        float v = tsum;
        #pragma unroll
        for (int o = 1; o < 32; o <<= 1) {
            float t = __shfl_up_sync(0xffffffffu, v, o);
            if (lane >= o) v += t;
        }
        if (lane == 31) s_redA[wid] = v;
        __syncthreads();
        if (wid == 0) {
            float t = s_redA[lane];
            #pragma unroll
            for (int o = 1; o < 32; o <<= 1) {
                float u = __shfl_up_sync(0xffffffffu, t, o);
                if (lane >= o) t += u;
            }
            s_redA[lane] = t;
        }
        __syncthreads();
        const float woff = (wid > 0) ? s_redA[wid - 1] : 0.f;
        const float toff = woff + (v - tsum);
        #pragma unroll
        for (int j = 0; j < 8; j++) s_val[base + j] = toff + loc[j];
    }
    __syncthreads();

    // ---- Phase F: ecdf on the 3N grid. lower_bound accelerated by bucket
    //      offsets: answer lies in [off[bk], off[bk+1]] (monotone mapping). ----
    const double step = 3.0 / (double)(G - 1);
    for (int g = tid; g < G; g += TPB) {
        float xn = (float)(-1.0 + step * (double)g);
        float fx = floorf(xn);
        float r  = xn - fx;                       // in [0,1)
        int bk = (int)(r * (float)NB);
        bk = bk < 0 ? 0 : (bk > NB - 1 ? NB - 1 : bk);
        int lb = s_off[bk], hi = s_off[bk + 1];
        while (lb < hi && s_key[lb] < r) lb++;    // expected ~1 iteration
        int idx = lb - 1;
        idx = idx < 0 ? 0 : (idx > NS - 2 ? NS - 2 : idx);
        float x0 = s_key[idx], x1v = s_key[idx + 1];
        float y0 = s_val[idx], y1v = s_val[idx + 1];
        float t  = (r - x0) / (x1v - x0);
        s_ecdf[g] = fx + (y0 + t * (y1v - y0));
    }
    __syncthreads();

    // ---- Phase G: invert ecdf at queries q_i = i/N - alpha (sorted ->
    //      binary search once per 8-query chunk, then merge-advance) ----
    const float alpha = s_alpha;
    float* __restrict__ hout = g_h + (size_t)b * NREF;
    int lb;
    {
        float q0 = (float)(tid * 8) * (1.0f / NREF) - alpha;
        int lo = 0, hi2 = G;
        while (lo < hi2) {
            int mid = (lo + hi2) >> 1;
            if (s_ecdf[mid] < q0) lo = mid + 1; else hi2 = mid;
        }
        lb = lo;
    }
    #pragma unroll
    for (int j = 0; j < 8; j++) {
        int i = tid * 8 + j;
        float refv = (float)i * (1.0f / NREF);
        float q = refv - alpha;
        while (lb < G && s_ecdf[lb] < q) lb++;
        int idx = lb - 1;
        idx = idx < 0 ? 0 : (idx > G - 2 ? G - 2 : idx);
        float e0 = s_ecdf[idx], e1 = s_ecdf[idx + 1];
        float xn0 = (float)(-1.0 + step * (double)idx);
        float xn1 = (float)(-1.0 + step * (double)(idx + 1));
        float t = (q - e0) / (e1 - e0);
        hout[i] = xn0 + t * (xn1 - xn0) - refv;
    }
}

// ---------------------------------------------------------------------------
// Reduce: per-row sum of min(d, 1-d)^2   (no atomics -> deterministic)
// ---------------------------------------------------------------------------
extern "C" __global__ void lcot_reduce_kernel()
{
    const int row = blockIdx.x;                 // 0..511
    const float* __restrict__ h1 = g_h + (size_t)row * NREF;
    const float* __restrict__ h2 = g_h + (size_t)(L + row) * NREF;
    float s = 0.f;
    for (int i = threadIdx.x; i < NREF; i += blockDim.x) {
        float d = fabsf(h2[i] - h1[i]);
        float m = fminf(d, 1.0f - d);
        s += m * m;
    }
    #pragma unroll
    for (int o = 16; o; o >>= 1) s += __shfl_down_sync(0xffffffffu, s, o);
    __shared__ float r[8];
    int lane = threadIdx.x & 31, wid = threadIdx.x >> 5;
    if (lane == 0) r[wid] = s;
    __syncthreads();
    if (threadIdx.x == 0) {
        float tot = 0.f;
        #pragma unroll
        for (int i = 0; i < 8; i++) tot += r[i];
        g_rowsum[row] = tot;
    }
}

// Finalize: deterministic fixed-tree sum of 512 row sums, sqrt(mean)
extern "C" __global__ void lcot_fin_kernel(float* __restrict__ out)
{
    __shared__ double sd[512];
    sd[threadIdx.x] = (double)g_rowsum[threadIdx.x];
    __syncthreads();
    #pragma unroll
    for (int o = 256; o; o >>= 1) {
        if (threadIdx.x < o) sd[threadIdx.x] += sd[threadIdx.x + o];
        __syncthreads();
    }
    if (threadIdx.x == 0) out[0] = (float)sqrt(sd[0] / (double)L);
}

extern "C" void kernel_launch(void* const* d_in, const int* in_sizes, int n_in,
                              void* d_out, int out_size)
{
    const float* x1 = (const float*)d_in[0];
    const float* w1 = (const float*)d_in[1];
    const float* x2 = (const float*)d_in[2];
    const float* w2 = (const float*)d_in[3];
    float* out = (float*)d_out;

    const size_t smem = (size_t)(2 * NS + G) * sizeof(float)
                      + (size_t)(NB + 1) * sizeof(int);   // 196612 bytes
    cudaFuncSetAttribute(lcot_row_kernel,
                         cudaFuncAttributeMaxDynamicSharedMemorySize, (int)smem);

    lcot_row_kernel<<<2 * L, TPB, smem>>>(x1, w1, x2, w2);
    lcot_reduce_kernel<<<L, 256>>>();
    lcot_fin_kernel<<<1, 512>>>(out);
}